// round 3
// baseline (speedup 1.0000x reference)
#include <cuda_runtime.h>

#define TILE  32
#define HALO  5
#define NR    42              // halo tile rows/cols (TILE + 2*HALO)
#define PADW  44              // padded smem row width (float4-friendly)
#define IMG   512
#define BATCH 32
#define NBLK  (16*16*32)      // 8192 blocks

typedef unsigned long long u64;

__device__ double       g_accum;   // zero-init at module load; reset by last block
__device__ unsigned int g_count;

// Gaussian window (ws=11, sigma=1.5), normalized — matches jnp float32 chain
__device__ __forceinline__ float gw(int k) {
    const float G[11] = {0.00102838f, 0.00759876f, 0.03600077f, 0.10936069f,
                         0.21300554f, 0.26601173f, 0.21300554f, 0.10936069f,
                         0.03600077f, 0.00759876f, 0.00102838f};
    return G[k];
}

// ---- f32x2 packed helpers (register-pair views; pack/unpack are free) ----
__device__ __forceinline__ u64 pk2(float lo, float hi) {
    return ((u64)__float_as_uint(hi) << 32) | (u64)__float_as_uint(lo);
}
__device__ __forceinline__ float lo2(u64 v) { return __uint_as_float((unsigned)v); }
__device__ __forceinline__ float hi2(u64 v) { return __uint_as_float((unsigned)(v >> 32)); }
__device__ __forceinline__ u64 fma2(u64 a, u64 b, u64 c) {
    u64 d; asm("fma.rn.f32x2 %0, %1, %2, %3;" : "=l"(d) : "l"(a), "l"(b), "l"(c));
    return d;
}
__device__ __forceinline__ u64 mul2(u64 a, u64 b) {
    u64 d; asm("mul.rn.f32x2 %0, %1, %2;" : "=l"(d) : "l"(a), "l"(b));
    return d;
}

__global__ __launch_bounds__(256, 4)
void ssim_main_kernel(const float* __restrict__ pred,
                      const float* __restrict__ targ,
                      float* __restrict__ out)
{
    __shared__ __align__(16) float  sP[NR * PADW];
    __shared__ __align__(16) float  sT[NR * PADW];
    __shared__ __align__(16) float4 hA[NR * TILE];   // (mu1h, mu2h, e11h, e22h)
    __shared__ __align__(16) float  hB[NR * TILE];   // e12h
    __shared__ float red[8];

    const int tid = threadIdx.x;                 // 0..255
    const int n  = blockIdx.z;
    const int x0 = blockIdx.x * TILE - HALO;
    const int y0 = blockIdx.y * TILE - HALO;
    const float* __restrict__ pbase = pred + (size_t)n * IMG * IMG;
    const float* __restrict__ tbase = targ + (size_t)n * IMG * IMG;

    // ---- Phase 1: load 42x42 halo tiles into padded smem (zero-pad OOB)
    for (int idx = tid; idx < NR * NR; idx += 256) {
        int r = idx / NR, c = idx - r * NR;
        int gy = y0 + r, gx = x0 + c;
        float p = 0.f, t = 0.f;
        if ((unsigned)gx < IMG && (unsigned)gy < IMG) {
            p = __ldg(pbase + gy * IMG + gx);
            t = __ldg(tbase + gy * IMG + gx);
        }
        sP[r * PADW + c] = p;
        sT[r * PADW + c] = t;
    }
    __syncthreads();

    // ---- Phase 2: horizontal blur, 4 consecutive cols per item, packed (p,t)
    for (int it = tid; it < NR * 8; it += 256) {
        int r = it >> 3;
        int q = it & 7;
        const float4* vp = (const float4*)(sP + r * PADW + q * 4);
        const float4* vt = (const float4*)(sT + r * PADW + q * 4);
        float4 A0 = vp[0], A1 = vp[1], A2 = vp[2], A3 = vp[3];
        float4 B0 = vt[0], B1 = vt[1], B2 = vt[2], B3 = vt[3];

        u64 w[14];
        w[0]  = pk2(A0.x, B0.x); w[1]  = pk2(A0.y, B0.y);
        w[2]  = pk2(A0.z, B0.z); w[3]  = pk2(A0.w, B0.w);
        w[4]  = pk2(A1.x, B1.x); w[5]  = pk2(A1.y, B1.y);
        w[6]  = pk2(A1.z, B1.z); w[7]  = pk2(A1.w, B1.w);
        w[8]  = pk2(A2.x, B2.x); w[9]  = pk2(A2.y, B2.y);
        w[10] = pk2(A2.z, B2.z); w[11] = pk2(A2.w, B2.w);
        w[12] = pk2(A3.x, B3.x); w[13] = pk2(A3.y, B3.y);

        u64 s12[4] = {0ull, 0ull, 0ull, 0ull};    // (mu1h, mu2h)
        u64 s34[4] = {0ull, 0ull, 0ull, 0ull};    // (e11h, e22h)
        float s5[4] = {0.f, 0.f, 0.f, 0.f};       // e12h

        #pragma unroll
        for (int k = 0; k < 14; k++) {
            u64 sq = mul2(w[k], w[k]);             // (p^2, t^2)
            float ptv = lo2(w[k]) * hi2(w[k]);     // p*t
            #pragma unroll
            for (int i = 0; i < 4; i++) {
                int kk = k - i;
                if (kk >= 0 && kk < 11) {
                    float g = gw(kk);
                    u64 g2 = pk2(g, g);            // compile-time constant
                    s12[i] = fma2(g2, w[k], s12[i]);
                    s34[i] = fma2(g2, sq,   s34[i]);
                    s5[i]  = fmaf(g, ptv, s5[i]);
                }
            }
        }

        int ho = r * TILE + q * 4;
        #pragma unroll
        for (int i = 0; i < 4; i++) {
            hA[ho + i] = make_float4(lo2(s12[i]), hi2(s12[i]),
                                     lo2(s34[i]), hi2(s34[i]));
            hB[ho + i] = s5[i];
        }
    }
    __syncthreads();

    // ---- Phase 3: vertical blur + SSIM, 4 consecutive rows per thread
    const int tx = tid & 31;
    const int ty = tid >> 5;                     // 0..7
    const int rbase = ty * 4;                    // output rows rbase..rbase+3

    u64 m[4]  = {0ull, 0ull, 0ull, 0ull};        // (mu1, mu2)
    u64 e[4]  = {0ull, 0ull, 0ull, 0ull};        // (e11, e22)
    float c12[4] = {0.f, 0.f, 0.f, 0.f};         // e12

    #pragma unroll
    for (int j = 0; j < 14; j++) {
        float4 v = hA[(rbase + j) * TILE + tx];
        float v5 = hB[(rbase + j) * TILE + tx];
        u64 wm = pk2(v.x, v.y);
        u64 we = pk2(v.z, v.w);
        #pragma unroll
        for (int i = 0; i < 4; i++) {
            int k = j - i;
            if (k >= 0 && k < 11) {
                float g = gw(k);
                u64 g2 = pk2(g, g);
                m[i]   = fma2(g2, wm, m[i]);
                e[i]   = fma2(g2, we, e[i]);
                c12[i] = fmaf(g, v5, c12[i]);
            }
        }
    }

    float acc = 0.f;
    #pragma unroll
    for (int i = 0; i < 4; i++) {
        float m1 = lo2(m[i]), m2 = hi2(m[i]);
        float e11 = lo2(e[i]), e22 = hi2(e[i]);
        float mu1s = m1 * m1;
        float mu2s = m2 * m2;
        float mu12 = m1 * m2;
        float v1 = e11 - mu1s;                   // sigma1_sq
        float v2 = e22 - mu2s;                   // sigma2_sq
        float cv = c12[i] - mu12;                // sigma12
        const float C1 = 1e-4f;                  // 0.01^2
        const float C2 = 9e-4f;                  // 0.03^2
        float num = (2.f * mu12 + C1) * (2.f * cv + C2);
        float den = (mu1s + mu2s + C1) * (v1 + v2 + C2);
        acc += __fdividef(num, den);
    }

    // ---- Phase 4: block reduce, then last-block finalize (no 2nd kernel)
    #pragma unroll
    for (int o = 16; o > 0; o >>= 1)
        acc += __shfl_xor_sync(0xffffffffu, acc, o);
    if ((tid & 31) == 0) red[tid >> 5] = acc;
    __syncthreads();
    if (tid == 0) {
        float v = red[0] + red[1] + red[2] + red[3] +
                  red[4] + red[5] + red[6] + red[7];
        atomicAdd(&g_accum, (double)v);
        __threadfence();
        unsigned old = atomicAdd(&g_count, 1u);
        if (old == NBLK - 1) {
            __threadfence();
            double s = *((volatile double*)&g_accum);
            out[0] = (float)(1.0 - s / ((double)BATCH * IMG * IMG));
            g_accum = 0.0;                       // reset for next graph replay
            g_count = 0u;
        }
    }
}

extern "C" void kernel_launch(void* const* d_in, const int* in_sizes, int n_in,
                              void* d_out, int out_size)
{
    const float* pred = (const float*)d_in[0];
    const float* targ = (const float*)d_in[1];
    float* out = (float*)d_out;

    dim3 grid(IMG / TILE, IMG / TILE, BATCH);    // 16 x 16 x 32
    ssim_main_kernel<<<grid, 256>>>(pred, targ, out);
}

// round 4
// speedup vs baseline: 1.1754x; 1.1754x over previous
#include <cuda_runtime.h>

#define TILE  32
#define HALO  5
#define NR    42              // halo tile rows/cols (TILE + 2*HALO)
#define PADW2 44              // padded smem row width in float2 units
#define IMG   512
#define BATCH 32
#define NBLK  (16*16*32)      // 8192 blocks

typedef unsigned long long u64;

__device__ double       g_accum;   // zero at module load; reset by last block
__device__ unsigned int g_count;

// Gaussian window (ws=11, sigma=1.5), normalized — matches jnp float32 chain
__device__ __forceinline__ float gw(int k) {
    const float G[11] = {0.00102838f, 0.00759876f, 0.03600077f, 0.10936069f,
                         0.21300554f, 0.26601173f, 0.21300554f, 0.10936069f,
                         0.03600077f, 0.00759876f, 0.00102838f};
    return G[k];
}

// ---- f32x2 helpers: register-pair views, NO integer shifts ----
__device__ __forceinline__ u64 pk2(float lo, float hi) {
    u64 d; asm("mov.b64 %0, {%1, %2};" : "=l"(d) : "f"(lo), "f"(hi));
    return d;
}
__device__ __forceinline__ void upk2(u64 v, float& lo, float& hi) {
    asm("mov.b64 {%0, %1}, %2;" : "=f"(lo), "=f"(hi) : "l"(v));
}
__device__ __forceinline__ u64 fma2(u64 a, u64 b, u64 c) {
    u64 d; asm("fma.rn.f32x2 %0, %1, %2, %3;" : "=l"(d) : "l"(a), "l"(b), "l"(c));
    return d;
}
__device__ __forceinline__ u64 mul2(u64 a, u64 b) {
    u64 d; asm("mul.rn.f32x2 %0, %1, %2;" : "=l"(d) : "l"(a), "l"(b));
    return d;
}

__global__ __launch_bounds__(256, 4)
void ssim_main_kernel(const float* __restrict__ pred,
                      const float* __restrict__ targ,
                      float* __restrict__ out)
{
    // (p,t) interleaved pairs
    __shared__ __align__(16) float2     sPT[NR * PADW2];        // 14.8 KB
    // (mu1h,mu2h) | (e11h,e22h) packed pairs
    __shared__ __align__(16) ulonglong2 hA[NR * TILE];          // 21.5 KB
    __shared__ __align__(16) float      hB[NR * TILE];          // 5.4 KB (e12h)
    __shared__ float red[8];

    const int tid = threadIdx.x;                 // 0..255
    const int n  = blockIdx.z;
    const int x0 = blockIdx.x * TILE - HALO;
    const int y0 = blockIdx.y * TILE - HALO;
    const float* __restrict__ pbase = pred + (size_t)n * IMG * IMG;
    const float* __restrict__ tbase = targ + (size_t)n * IMG * IMG;

    // ---- Phase 1: load halo tile, store (p,t) interleaved (zero-pad OOB)
    for (int idx = tid; idx < NR * NR; idx += 256) {
        int r = idx / NR, c = idx - r * NR;
        int gy = y0 + r, gx = x0 + c;
        float p = 0.f, t = 0.f;
        if ((unsigned)gx < IMG && (unsigned)gy < IMG) {
            p = __ldg(pbase + gy * IMG + gx);
            t = __ldg(tbase + gy * IMG + gx);
        }
        sPT[r * PADW2 + c] = make_float2(p, t);
    }
    __syncthreads();

    // ---- Phase 2: horizontal blur, 4 consecutive cols per item, packed (p,t)
    for (int it = tid; it < NR * 8; it += 256) {
        int r = it >> 3;
        int q = it & 7;
        // 14-pair window, loaded as 7x LDS.128 (naturally aligned reg pairs)
        const ulonglong2* vw = (const ulonglong2*)(sPT + r * PADW2 + q * 4);
        u64 w[14];
        #pragma unroll
        for (int j = 0; j < 7; j++) {
            ulonglong2 v = vw[j];
            w[2 * j]     = v.x;
            w[2 * j + 1] = v.y;
        }

        u64 s12[4] = {0ull, 0ull, 0ull, 0ull};    // (mu1h, mu2h)
        u64 s34[4] = {0ull, 0ull, 0ull, 0ull};    // (e11h, e22h)
        float s5[4] = {0.f, 0.f, 0.f, 0.f};       // e12h

        #pragma unroll
        for (int k = 0; k < 14; k++) {
            u64 sq = mul2(w[k], w[k]);             // (p^2, t^2)
            float pv, tv;
            upk2(w[k], pv, tv);                    // register halves, ~free
            float ptv = pv * tv;                   // p*t
            #pragma unroll
            for (int i = 0; i < 4; i++) {
                int kk = k - i;
                if (kk >= 0 && kk < 11) {
                    float g = gw(kk);
                    u64 g2 = pk2(g, g);            // constant pair
                    s12[i] = fma2(g2, w[k], s12[i]);
                    s34[i] = fma2(g2, sq,   s34[i]);
                    s5[i]  = fmaf(g, ptv, s5[i]);
                }
            }
        }

        int ho = r * TILE + q * 4;
        #pragma unroll
        for (int i = 0; i < 4; i++) {
            hA[ho + i] = make_ulonglong2(s12[i], s34[i]);  // STS.128
            hB[ho + i] = s5[i];
        }
    }
    __syncthreads();

    // ---- Phase 3: vertical blur + SSIM, 4 consecutive rows per thread
    const int tx = tid & 31;
    const int ty = tid >> 5;                     // 0..7
    const int rbase = ty * 4;                    // output rows rbase..rbase+3

    u64 m[4]  = {0ull, 0ull, 0ull, 0ull};        // (mu1, mu2)
    u64 e[4]  = {0ull, 0ull, 0ull, 0ull};        // (e11, e22)
    float c12[4] = {0.f, 0.f, 0.f, 0.f};         // e12

    #pragma unroll
    for (int j = 0; j < 14; j++) {
        ulonglong2 v = hA[(rbase + j) * TILE + tx];   // LDS.128 -> 2 reg pairs
        float v5 = hB[(rbase + j) * TILE + tx];
        #pragma unroll
        for (int i = 0; i < 4; i++) {
            int k = j - i;
            if (k >= 0 && k < 11) {
                float g = gw(k);
                u64 g2 = pk2(g, g);
                m[i]   = fma2(g2, v.x, m[i]);
                e[i]   = fma2(g2, v.y, e[i]);
                c12[i] = fmaf(g, v5, c12[i]);
            }
        }
    }

    float acc = 0.f;
    #pragma unroll
    for (int i = 0; i < 4; i++) {
        float m1, m2, e11, e22;
        upk2(m[i], m1, m2);
        upk2(e[i], e11, e22);
        float mu1s = m1 * m1;
        float mu2s = m2 * m2;
        float mu12 = m1 * m2;
        float v1 = e11 - mu1s;                   // sigma1_sq
        float v2 = e22 - mu2s;                   // sigma2_sq
        float cv = c12[i] - mu12;                // sigma12
        const float C1 = 1e-4f;                  // 0.01^2
        const float C2 = 9e-4f;                  // 0.03^2
        float num = (2.f * mu12 + C1) * (2.f * cv + C2);
        float den = (mu1s + mu2s + C1) * (v1 + v2 + C2);
        acc += __fdividef(num, den);
    }

    // ---- Phase 4: block reduce, last-block finalize (single kernel)
    #pragma unroll
    for (int o = 16; o > 0; o >>= 1)
        acc += __shfl_xor_sync(0xffffffffu, acc, o);
    if ((tid & 31) == 0) red[tid >> 5] = acc;
    __syncthreads();
    if (tid == 0) {
        float v = red[0] + red[1] + red[2] + red[3] +
                  red[4] + red[5] + red[6] + red[7];
        atomicAdd(&g_accum, (double)v);
        __threadfence();
        unsigned old = atomicAdd(&g_count, 1u);
        if (old == NBLK - 1) {
            __threadfence();
            double s = *((volatile double*)&g_accum);
            out[0] = (float)(1.0 - s / ((double)BATCH * IMG * IMG));
            g_accum = 0.0;                       // reset for next graph replay
            g_count = 0u;
        }
    }
}

extern "C" void kernel_launch(void* const* d_in, const int* in_sizes, int n_in,
                              void* d_out, int out_size)
{
    const float* pred = (const float*)d_in[0];
    const float* targ = (const float*)d_in[1];
    float* out = (float*)d_out;

    dim3 grid(IMG / TILE, IMG / TILE, BATCH);    // 16 x 16 x 32
    ssim_main_kernel<<<grid, 256>>>(pred, targ, out);
}

// round 5
// speedup vs baseline: 1.2943x; 1.1012x over previous
#include <cuda_runtime.h>

#define TILE  32
#define HALO  5
#define NR    42              // halo tile rows/cols (TILE + 2*HALO)
#define PADW2 44              // padded smem row width in float2 units
#define IMG   512
#define BATCH 32
#define NBLK  (16*16*32)      // 8192 blocks

typedef unsigned long long u64;

__device__ double       g_accum;   // zero at module load; reset by last block
__device__ unsigned int g_count;

// Gaussian window (ws=11, sigma=1.5), normalized — matches jnp float32 chain
__device__ __forceinline__ float gw(int k) {
    const float G[11] = {0.00102838f, 0.00759876f, 0.03600077f, 0.10936069f,
                         0.21300554f, 0.26601173f, 0.21300554f, 0.10936069f,
                         0.03600077f, 0.00759876f, 0.00102838f};
    return G[k];
}

// ---- f32x2 helpers: register-pair views, NO integer shifts ----
__device__ __forceinline__ u64 pk2(float lo, float hi) {
    u64 d; asm("mov.b64 %0, {%1, %2};" : "=l"(d) : "f"(lo), "f"(hi));
    return d;
}
__device__ __forceinline__ void upk2(u64 v, float& lo, float& hi) {
    asm("mov.b64 {%0, %1}, %2;" : "=f"(lo), "=f"(hi) : "l"(v));
}
__device__ __forceinline__ u64 fma2(u64 a, u64 b, u64 c) {
    u64 d; asm("fma.rn.f32x2 %0, %1, %2, %3;" : "=l"(d) : "l"(a), "l"(b), "l"(c));
    return d;
}
__device__ __forceinline__ u64 mul2(u64 a, u64 b) {
    u64 d; asm("mul.rn.f32x2 %0, %1, %2;" : "=l"(d) : "l"(a), "l"(b));
    return d;
}

__global__ __launch_bounds__(256, 5)
void ssim_main_kernel(const float* __restrict__ pred,
                      const float* __restrict__ targ,
                      float* __restrict__ out)
{
    // (s,d) = (p+t, p-t) interleaved pairs
    __shared__ __align__(16) float2     sSD[NR * PADW2];        // 14.8 KB
    // packed horizontal blurs: ( (mu_s,mu_d) , (E_ss,E_dd) )
    __shared__ __align__(16) ulonglong2 hA[NR * TILE];          // 21.5 KB
    __shared__ float red[8];

    const int tid = threadIdx.x;                 // 0..255
    const int n  = blockIdx.z;
    const int x0 = blockIdx.x * TILE - HALO;
    const int y0 = blockIdx.y * TILE - HALO;
    const float* __restrict__ pbase = pred + (size_t)n * IMG * IMG;
    const float* __restrict__ tbase = targ + (size_t)n * IMG * IMG;

    // ---- Phase 1: load halo tile, store (s,d) interleaved (zero-pad OOB)
    for (int idx = tid; idx < NR * NR; idx += 256) {
        int r = idx / NR, c = idx - r * NR;
        int gy = y0 + r, gx = x0 + c;
        float p = 0.f, t = 0.f;
        if ((unsigned)gx < IMG && (unsigned)gy < IMG) {
            p = __ldg(pbase + gy * IMG + gx);
            t = __ldg(tbase + gy * IMG + gx);
        }
        sSD[r * PADW2 + c] = make_float2(p + t, p - t);
    }
    __syncthreads();

    // ---- Phase 2: horizontal blur of (s,d) and (s^2,d^2), 4 cols per item
    for (int it = tid; it < NR * 8; it += 256) {
        int r = it >> 3;
        int q = it & 7;
        // 14-pair window: 7x LDS.128 (aligned register pairs)
        const ulonglong2* vw = (const ulonglong2*)(sSD + r * PADW2 + q * 4);
        u64 w[14];
        #pragma unroll
        for (int j = 0; j < 7; j++) {
            ulonglong2 v = vw[j];
            w[2 * j]     = v.x;
            w[2 * j + 1] = v.y;
        }

        u64 sm[4] = {0ull, 0ull, 0ull, 0ull};    // (mu_s_h, mu_d_h)
        u64 se[4] = {0ull, 0ull, 0ull, 0ull};    // (E_ss_h, E_dd_h)

        #pragma unroll
        for (int k = 0; k < 14; k++) {
            u64 sq = mul2(w[k], w[k]);           // (s^2, d^2)
            #pragma unroll
            for (int i = 0; i < 4; i++) {
                int kk = k - i;
                if (kk >= 0 && kk < 11) {
                    float g = gw(kk);
                    u64 g2 = pk2(g, g);          // compile-time constant pair
                    sm[i] = fma2(g2, w[k], sm[i]);
                    se[i] = fma2(g2, sq,   se[i]);
                }
            }
        }

        int ho = r * TILE + q * 4;
        #pragma unroll
        for (int i = 0; i < 4; i++)
            hA[ho + i] = make_ulonglong2(sm[i], se[i]);   // STS.128
    }
    __syncthreads();

    // ---- Phase 3: vertical blur + SSIM, 4 consecutive rows per thread
    const int tx = tid & 31;
    const int ty = tid >> 5;                     // 0..7
    const int rbase = ty * 4;                    // output rows rbase..rbase+3

    u64 m[4] = {0ull, 0ull, 0ull, 0ull};         // (mu_s, mu_d)
    u64 e[4] = {0ull, 0ull, 0ull, 0ull};         // (E_ss, E_dd)

    #pragma unroll
    for (int j = 0; j < 14; j++) {
        ulonglong2 v = hA[(rbase + j) * TILE + tx];   // LDS.128
        #pragma unroll
        for (int i = 0; i < 4; i++) {
            int k = j - i;
            if (k >= 0 && k < 11) {
                float g = gw(k);
                u64 g2 = pk2(g, g);
                m[i] = fma2(g2, v.x, m[i]);
                e[i] = fma2(g2, v.y, e[i]);
            }
        }
    }

    float acc = 0.f;
    #pragma unroll
    for (int i = 0; i < 4; i++) {
        u64 msq = mul2(m[i], m[i]);              // (mu_s^2, mu_d^2)
        float ms2, md2, Ess, Edd;
        upk2(msq, ms2, md2);
        upk2(e[i], Ess, Edd);
        // 2*mu1mu2      = (ms2 - md2)/2
        // mu1^2+mu2^2   = (ms2 + md2)/2
        // 2*sigma12     = (Ess - Edd)/2 - (ms2 - md2)/2
        // v1+v2         = (Ess + Edd)/2 - (ms2 + md2)/2
        const float C1 = 1e-4f;                  // 0.01^2
        const float C2 = 9e-4f;                  // 0.03^2
        float B = 0.5f * (ms2 - md2);
        float A = 0.5f * (ms2 + md2);
        float num = (B + C1) * (0.5f * (Ess - Edd) - B + C2);
        float den = (A + C1) * (0.5f * (Ess + Edd) - A + C2);
        acc += __fdividef(num, den);
    }

    // ---- Phase 4: block reduce, last-block finalize (single kernel)
    #pragma unroll
    for (int o = 16; o > 0; o >>= 1)
        acc += __shfl_xor_sync(0xffffffffu, acc, o);
    if ((tid & 31) == 0) red[tid >> 5] = acc;
    __syncthreads();
    if (tid == 0) {
        float v = red[0] + red[1] + red[2] + red[3] +
                  red[4] + red[5] + red[6] + red[7];
        atomicAdd(&g_accum, (double)v);
        __threadfence();
        unsigned old = atomicAdd(&g_count, 1u);
        if (old == NBLK - 1) {
            __threadfence();
            double s = *((volatile double*)&g_accum);
            out[0] = (float)(1.0 - s / ((double)BATCH * IMG * IMG));
            g_accum = 0.0;                       // reset for next graph replay
            g_count = 0u;
        }
    }
}

extern "C" void kernel_launch(void* const* d_in, const int* in_sizes, int n_in,
                              void* d_out, int out_size)
{
    const float* pred = (const float*)d_in[0];
    const float* targ = (const float*)d_in[1];
    float* out = (float*)d_out;

    dim3 grid(IMG / TILE, IMG / TILE, BATCH);    // 16 x 16 x 32
    ssim_main_kernel<<<grid, 256>>>(pred, targ, out);
}